// round 7
// baseline (speedup 1.0000x reference)
#include <cuda_runtime.h>

#define NC 128
#define EPS 1e-5f
#define RAYS_PER_CTA 8          // 8 warps/CTA, one ray per warp
#define THREADS (RAYS_PER_CTA * 32)

__global__ __launch_bounds__(THREADS) void pdf_sampler_kernel(
    const float* __restrict__ deltas,
    const float* __restrict__ density,
    const float* __restrict__ bins,
    const float* __restrict__ u,
    float* __restrict__ out)
{
    const int lane = threadIdx.x & 31;
    const int wrp  = threadIdx.x >> 5;
    const int ray  = blockIdx.x * RAYS_PER_CTA + wrp;

    // cd[i] = cdf[i+1], i=0..127 (search probes)
    __shared__ __align__(16) float  cd_sh[RAYS_PER_CTA][NC];
    // cpair[p] = (cdf[p], cdf[p+1]), p=0..127  -> c0,c1 in one LDS.64
    __shared__ __align__(16) float2 cpair_sh[RAYS_PER_CTA][NC];
    // bpair[p] = (bins[p], bins[p+1]-bins[p]) -> b0, db in one LDS.64
    __shared__ __align__(16) float2 bpair_sh[RAYS_PER_CTA][NC];

    const size_t base_c = (size_t)ray * NC;

    // ---- coalesced loads (full bins row NOT loaded; only near) ----
    const float4 dv = *(const float4*)(deltas  + base_c + 4 * lane);
    const float4 rv = *(const float4*)(density + base_c + 4 * lane);
    const float4 uv = *(const float4*)(u       + base_c + 4 * lane);
    const float nearv = bins[(size_t)ray * (NC + 1)];   // warp-uniform

    // ---- per-lane serial prefixes: dd = delta*density, and delta ----
    const float dd0 = dv.x * rv.x;
    const float dd1 = dv.y * rv.y;
    const float dd2 = dv.z * rv.z;
    const float dd3 = dv.w * rv.w;
    const float pA0 = dd0, pA1 = pA0 + dd1, pA2 = pA1 + dd2, pA3 = pA2 + dd3;
    const float pD0 = dv.x, pD1 = pD0 + dv.y, pD2 = pD1 + dv.z, pD3 = pD2 + dv.w;

    // ---- fused dual warp scan over lane totals ----
    float sA = pA3, sD = pD3;
    #pragma unroll
    for (int o = 1; o < 32; o <<= 1) {
        const float nA = __shfl_up_sync(0xffffffffu, sA, o);
        const float nD = __shfl_up_sync(0xffffffffu, sD, o);
        if (lane >= o) { sA += nA; sD += nD; }
    }
    const float offA = sA - pA3;      // exclusive dd-cumsum at element e
    const float offD = sD - pD3;      // exclusive delta-cumsum at element e

    // ---- telescoped cdf: cumsum(w)[i] = 1 - exp(-cumsum(dd)[i]) ----
    const float total = __shfl_sync(0xffffffffu, sA, 31);
    const float wsum  = 1.0f - __expf(-total);
    const float pad   = fmaxf(EPS - wsum, 0.0f);
    const float inv   = __fdividef(1.0f, wsum + pad);
    const float ps    = pad * (1.0f / (float)NC);

    const int e = 4 * lane;
    float4 cv;
    cv.x = fminf(1.0f, (1.0f - __expf(-(offA + pA0)) + ps * (float)(e + 1)) * inv);
    cv.y = fminf(1.0f, (1.0f - __expf(-(offA + pA1)) + ps * (float)(e + 2)) * inv);
    cv.z = fminf(1.0f, (1.0f - __expf(-(offA + pA2)) + ps * (float)(e + 3)) * inv);
    cv.w = fminf(1.0f, (1.0f - __expf(-(offA + pA3)) + ps * (float)(e + 4)) * inv);

    // cdf[e] = previous lane's cv.w (0 for lane 0)
    const float cprev_raw = __shfl_up_sync(0xffffffffu, cv.w, 1);
    const float cprev = (lane == 0) ? 0.0f : cprev_raw;

    // ---- build shared structures: 5 aligned STS.128, conflict-bounded ----
    *(float4*)(&cd_sh[wrp][e]) = cv;
    *(float4*)(&cpair_sh[wrp][e])     = make_float4(cprev, cv.x, cv.x, cv.y);
    *(float4*)(&cpair_sh[wrp][e + 2]) = make_float4(cv.y,  cv.z, cv.z, cv.w);
    const float be0 = nearv + offD;
    *(float4*)(&bpair_sh[wrp][e])     = make_float4(be0,       dv.x, be0 + pD0, dv.y);
    *(float4*)(&bpair_sh[wrp][e + 2]) = make_float4(be0 + pD1, dv.z, be0 + pD2, dv.w);

    __syncwarp();

    const float*  __restrict__ cd = cd_sh[wrp];
    const float2* __restrict__ cp = cpair_sh[wrp];
    const float2* __restrict__ bp = bpair_sh[wrp];

    // hoisted level-1/2 probe values (broadcast loads, reused by all 4 samples)
    const float g64 = cd[63];
    const float g32 = cd[31];
    const float g96 = cd[95];

    float4 res;

    #pragma unroll
    for (int i = 0; i < 4; i++) {
        const float uu = (i == 0) ? uv.x : (i == 1) ? uv.y : (i == 2) ? uv.z : uv.w;

        // pos = #{cd[k] <= u} over cd[0..127]  (max 127 reachable)
        int pos = (g64 <= uu) ? 64 : 0;
        const float v2 = (g64 <= uu) ? g96 : g32;
        if (v2 <= uu) pos += 32;
        if (cd[pos + 15] <= uu) pos += 16;
        if (cd[pos +  7] <= uu) pos += 8;
        if (cd[pos +  3] <= uu) pos += 4;
        // pos is 4-aligned; one aligned LDS.128 resolves the last 2 levels
        const float4 v = *(const float4*)(cd + pos);
        pos += (int)(v.x <= uu) + (int)(v.y <= uu) + (int)(v.z <= uu);

        const float2 c = cp[pos];   // (cdf[pos], cdf[pos+1])
        const float2 b = bp[pos];   // (bins[pos], bins[pos+1]-bins[pos])

        float den = c.y - c.x;
        den = (den < EPS) ? 1.0f : den;
        const float s = fmaf(__fdividef(uu - c.x, den), b.y, b.x);
        if (i == 0) res.x = s; else if (i == 1) res.y = s; else if (i == 2) res.z = s; else res.w = s;
    }

    *(float4*)(out + base_c + 4 * lane) = res;
}

extern "C" void kernel_launch(void* const* d_in, const int* in_sizes, int n_in,
                              void* d_out, int out_size) {
    const float* deltas  = (const float*)d_in[0];
    const float* density = (const float*)d_in[1];
    const float* bins    = (const float*)d_in[2];
    const float* u       = (const float*)d_in[3];
    float* out = (float*)d_out;

    int R = in_sizes[0] / NC;               // 131072
    pdf_sampler_kernel<<<R / RAYS_PER_CTA, THREADS>>>(deltas, density, bins, u, out);
}

// round 8
// speedup vs baseline: 1.1623x; 1.1623x over previous
#include <cuda_runtime.h>

#define NC 128
#define EPS 1e-5f
#define RAYS_PER_CTA 8          // 8 warps/CTA, one ray per warp
#define THREADS (RAYS_PER_CTA * 32)

__global__ __launch_bounds__(THREADS) void pdf_sampler_kernel(
    const float* __restrict__ deltas,
    const float* __restrict__ density,
    const float* __restrict__ bins,
    const float* __restrict__ u,
    float* __restrict__ out)
{
    const int lane = threadIdx.x & 31;
    const int wrp  = threadIdx.x >> 5;
    const int ray  = blockIdx.x * RAYS_PER_CTA + wrp;

    // cdf_full[p] = cdf[p], p = 0..128 (129 entries; row padded to 132 for alignment)
    __shared__ __align__(16) float cdf_sh[RAYS_PER_CTA][132];
    // bins[0..127] (b1 never gathered: b1-b0 = deltas[pos])
    __shared__ __align__(16) float bins_sh[RAYS_PER_CTA][NC];
    // raw deltas[0..127]
    __shared__ __align__(16) float ds_sh[RAYS_PER_CTA][NC];

    const size_t base_c = (size_t)ray * NC;

    // ---- coalesced loads (full bins row NOT loaded; only near) ----
    const float4 dv = *(const float4*)(deltas  + base_c + 4 * lane);
    const float4 rv = *(const float4*)(density + base_c + 4 * lane);
    const float4 uv = *(const float4*)(u       + base_c + 4 * lane);
    const float nearv = bins[(size_t)ray * (NC + 1)];   // warp-uniform

    // ---- per-lane serial prefixes: dd = delta*density, and delta ----
    const float dd0 = dv.x * rv.x;
    const float dd1 = dv.y * rv.y;
    const float dd2 = dv.z * rv.z;
    const float dd3 = dv.w * rv.w;
    const float pA0 = dd0, pA1 = pA0 + dd1, pA2 = pA1 + dd2, pA3 = pA2 + dd3;
    const float pD0 = dv.x, pD1 = pD0 + dv.y, pD2 = pD1 + dv.z, pD3 = pD2 + dv.w;

    // ---- fused dual warp scan over lane totals ----
    float sA = pA3, sD = pD3;
    #pragma unroll
    for (int o = 1; o < 32; o <<= 1) {
        const float nA = __shfl_up_sync(0xffffffffu, sA, o);
        const float nD = __shfl_up_sync(0xffffffffu, sD, o);
        if (lane >= o) { sA += nA; sD += nD; }
    }
    const float offA = sA - pA3;      // exclusive dd-cumsum at element e
    const float offD = sD - pD3;      // exclusive delta-cumsum at element e

    // ---- telescoped cdf: cumsum(w)[i] = 1 - exp(-cumsum(dd)[i]) ----
    const float total = __shfl_sync(0xffffffffu, sA, 31);
    const float wsum  = 1.0f - __expf(-total);
    const float pad   = fmaxf(EPS - wsum, 0.0f);
    const float inv   = __fdividef(1.0f, wsum + pad);
    const float ps    = pad * (1.0f / (float)NC);

    const int e = 4 * lane;
    float4 cv;
    cv.x = fminf(1.0f, (1.0f - __expf(-(offA + pA0)) + ps * (float)(e + 1)) * inv);
    cv.y = fminf(1.0f, (1.0f - __expf(-(offA + pA2 - pA1 + pA1)) + ps * (float)(e + 2)) * inv); // = offA+pA1
    cv.y = fminf(1.0f, (1.0f - __expf(-(offA + pA1)) + ps * (float)(e + 2)) * inv);
    cv.z = fminf(1.0f, (1.0f - __expf(-(offA + pA2)) + ps * (float)(e + 3)) * inv);
    cv.w = fminf(1.0f, (1.0f - __expf(-(offA + pA3)) + ps * (float)(e + 4)) * inv);

    // cdf[e] = previous lane's cv.w (0 for lane 0)
    const float cprev_raw = __shfl_up_sync(0xffffffffu, cv.w, 1);
    const float cprev = (lane == 0) ? 0.0f : cprev_raw;

    // ---- build shared: cdf_full[e..e+3], bins[e..e+3], deltas[e..e+3] ----
    *(float4*)(&cdf_sh[wrp][e]) = make_float4(cprev, cv.x, cv.y, cv.z);
    const float be0 = nearv + offD;
    *(float4*)(&bins_sh[wrp][e]) = make_float4(be0, be0 + pD0, be0 + pD1, be0 + pD2);
    *(float4*)(&ds_sh[wrp][e]) = dv;
    if (lane == 31) cdf_sh[wrp][NC] = cv.w;       // cdf[128]

    __syncwarp();

    const float* __restrict__ cf = cdf_sh[wrp];   // cdf_full
    const float* __restrict__ bn = bins_sh[wrp];
    const float* __restrict__ ds = ds_sh[wrp];

    // hoisted level-1/2 probe values (broadcast loads, reused by all 4 samples)
    const float g64 = cf[64];
    const float g32 = cf[32];
    const float g96 = cf[96];

    float4 res;

    #pragma unroll
    for (int i = 0; i < 4; i++) {
        const float uu = (i == 0) ? uv.x : (i == 1) ? uv.y : (i == 2) ? uv.z : uv.w;

        // pos = #{cdf[k] <= u, k=1..127-ish}; probes at cdf_full[pos+step]
        int pos = (g64 <= uu) ? 64 : 0;
        const float v2 = (g64 <= uu) ? g96 : g32;
        if (v2 <= uu) pos += 32;
        if (cf[pos + 16] <= uu) pos += 16;
        if (cf[pos +  8] <= uu) pos += 8;
        if (cf[pos +  4] <= uu) pos += 4;
        if (cf[pos +  2] <= uu) pos += 2;
        if (cf[pos +  1] <= uu) pos += 1;
        // pos in [0,127]

        const float c0 = cf[pos];          // cdf[pos]
        const float c1 = cf[pos + 1];      // cdf[pos+1]  (<= cf[128], valid)
        const float b0 = bn[pos];
        const float db = ds[pos];          // bins[pos+1] - bins[pos]

        float den = c1 - c0;
        den = (den < EPS) ? 1.0f : den;
        const float s = fmaf(__fdividef(uu - c0, den), db, b0);
        if (i == 0) res.x = s; else if (i == 1) res.y = s; else if (i == 2) res.z = s; else res.w = s;
    }

    *(float4*)(out + base_c + 4 * lane) = res;
}

extern "C" void kernel_launch(void* const* d_in, const int* in_sizes, int n_in,
                              void* d_out, int out_size) {
    const float* deltas  = (const float*)d_in[0];
    const float* density = (const float*)d_in[1];
    const float* bins    = (const float*)d_in[2];
    const float* u       = (const float*)d_in[3];
    float* out = (float*)d_out;

    int R = in_sizes[0] / NC;               // 131072
    pdf_sampler_kernel<<<R / RAYS_PER_CTA, THREADS>>>(deltas, density, bins, u, out);
}

// round 9
// speedup vs baseline: 1.1686x; 1.0054x over previous
#include <cuda_runtime.h>

#define NC 128
#define EPS 1e-5f
#define RAYS_PER_CTA 8          // 8 warps/CTA, one ray per warp
#define THREADS (RAYS_PER_CTA * 32)

__global__ __launch_bounds__(THREADS) void pdf_sampler_kernel(
    const float* __restrict__ deltas,
    const float* __restrict__ density,
    const float* __restrict__ bins,
    const float* __restrict__ u,
    float* __restrict__ out)
{
    const int lane = threadIdx.x & 31;
    const int wrp  = threadIdx.x >> 5;
    const int ray  = blockIdx.x * RAYS_PER_CTA + wrp;

    // cdf_full[p] = cdf[p], p = 0..128 (129 entries; row padded to 132)
    __shared__ __align__(16) float cdf_sh[RAYS_PER_CTA][132];
    __shared__ __align__(16) float bins_sh[RAYS_PER_CTA][NC];  // bins[0..127]
    __shared__ __align__(16) float ds_sh[RAYS_PER_CTA][NC];    // deltas[0..127]

    const size_t base_c = (size_t)ray * NC;

    // ---- coalesced loads (full bins row NOT loaded; only near) ----
    const float4 dv = *(const float4*)(deltas  + base_c + 4 * lane);
    const float4 rv = *(const float4*)(density + base_c + 4 * lane);
    const float4 uv = *(const float4*)(u       + base_c + 4 * lane);
    const float nearv = bins[(size_t)ray * (NC + 1)];   // warp-uniform

    // ---- per-lane serial prefixes: dd = delta*density, and delta ----
    const float dd0 = dv.x * rv.x;
    const float dd1 = dv.y * rv.y;
    const float dd2 = dv.z * rv.z;
    const float dd3 = dv.w * rv.w;
    const float pA0 = dd0, pA1 = pA0 + dd1, pA2 = pA1 + dd2, pA3 = pA2 + dd3;
    const float pD0 = dv.x, pD1 = pD0 + dv.y, pD2 = pD1 + dv.z, pD3 = pD2 + dv.w;

    // ---- fused dual warp scan over lane totals ----
    float sA = pA3, sD = pD3;
    #pragma unroll
    for (int o = 1; o < 32; o <<= 1) {
        const float nA = __shfl_up_sync(0xffffffffu, sA, o);
        const float nD = __shfl_up_sync(0xffffffffu, sD, o);
        if (lane >= o) { sA += nA; sD += nD; }
    }
    const float offA = sA - pA3;      // exclusive dd-cumsum at element e
    const float offD = sD - pD3;      // exclusive delta-cumsum at element e

    // ---- telescoped cdf: cumsum(w)[i] = 1 - exp(-cumsum(dd)[i]) ----
    const float total = __shfl_sync(0xffffffffu, sA, 31);
    const float wsum  = 1.0f - __expf(-total);
    const float pad   = fmaxf(EPS - wsum, 0.0f);
    const float inv   = __fdividef(1.0f, wsum + pad);
    const float ps    = pad * (1.0f / (float)NC);

    const int e = 4 * lane;
    float4 cv;
    cv.x = fminf(1.0f, (1.0f - __expf(-(offA + pA0)) + ps * (float)(e + 1)) * inv);
    cv.y = fminf(1.0f, (1.0f - __expf(-(offA + pA1)) + ps * (float)(e + 2)) * inv);
    cv.z = fminf(1.0f, (1.0f - __expf(-(offA + pA2)) + ps * (float)(e + 3)) * inv);
    cv.w = fminf(1.0f, (1.0f - __expf(-(offA + pA3)) + ps * (float)(e + 4)) * inv);

    // cdf[e] = previous lane's cv.w (0 for lane 0)
    const float cprev_raw = __shfl_up_sync(0xffffffffu, cv.w, 1);
    const float cprev = (lane == 0) ? 0.0f : cprev_raw;

    // ---- build shared: cdf_full[e..e+3], bins[e..e+3], deltas[e..e+3] ----
    *(float4*)(&cdf_sh[wrp][e]) = make_float4(cprev, cv.x, cv.y, cv.z);
    const float be0 = nearv + offD;
    *(float4*)(&bins_sh[wrp][e]) = make_float4(be0, be0 + pD0, be0 + pD1, be0 + pD2);
    *(float4*)(&ds_sh[wrp][e]) = dv;
    if (lane == 31) cdf_sh[wrp][NC] = cv.w;       // cdf[128]

    __syncwarp();

    const float* __restrict__ cf = cdf_sh[wrp];   // cdf_full
    const float* __restrict__ bn = bins_sh[wrp];
    const float* __restrict__ ds = ds_sh[wrp];

    // hoisted level-1/2 probe values (broadcast loads)
    const float g64 = cf[64];
    const float g32 = cf[32];
    const float g96 = cf[96];

    // ---- 4 interleaved binary searches: batch probes per level for MLP ----
    float uu[4] = { uv.x, uv.y, uv.z, uv.w };
    int pos[4];

    #pragma unroll
    for (int s = 0; s < 4; s++) {
        const bool l1 = (g64 <= uu[s]);
        pos[s] = l1 ? 64 : 0;
        const float v2 = l1 ? g96 : g32;
        if (v2 <= uu[s]) pos[s] += 32;
    }
    #pragma unroll
    for (int step = 16; step >= 1; step >>= 1) {
        float pv[4];
        #pragma unroll
        for (int s = 0; s < 4; s++) pv[s] = cf[pos[s] + step];   // 4 independent LDS
        #pragma unroll
        for (int s = 0; s < 4; s++) if (pv[s] <= uu[s]) pos[s] += step;
    }

    // ---- batched gathers ----
    float c0[4], c1[4], b0[4], db[4];
    #pragma unroll
    for (int s = 0; s < 4; s++) c0[s] = cf[pos[s]];
    #pragma unroll
    for (int s = 0; s < 4; s++) c1[s] = cf[pos[s] + 1];
    #pragma unroll
    for (int s = 0; s < 4; s++) b0[s] = bn[pos[s]];
    #pragma unroll
    for (int s = 0; s < 4; s++) db[s] = ds[pos[s]];

    float r[4];
    #pragma unroll
    for (int s = 0; s < 4; s++) {
        float den = c1[s] - c0[s];
        den = (den < EPS) ? 1.0f : den;
        r[s] = fmaf(__fdividef(uu[s] - c0[s], den), db[s], b0[s]);
    }

    *(float4*)(out + base_c + 4 * lane) = make_float4(r[0], r[1], r[2], r[3]);
}

extern "C" void kernel_launch(void* const* d_in, const int* in_sizes, int n_in,
                              void* d_out, int out_size) {
    const float* deltas  = (const float*)d_in[0];
    const float* density = (const float*)d_in[1];
    const float* bins    = (const float*)d_in[2];
    const float* u       = (const float*)d_in[3];
    float* out = (float*)d_out;

    int R = in_sizes[0] / NC;               // 131072
    pdf_sampler_kernel<<<R / RAYS_PER_CTA, THREADS>>>(deltas, density, bins, u, out);
}